// round 15
// baseline (speedup 1.0000x reference)
#include <cuda_runtime.h>
#include <cstdint>

#define NN 100000
#define EE 1600000
#define D 128
#define DOUT 64
#define NL 5
#define BN_EPS 1e-5

#define BM 128
#define BK 16
#define BMP 130                      // pad: conflict-free transposed STS, b64-aligned row pairs
#define GEMMB ((NN + BM - 1) / BM)   // 782 gemm tiles
#define TB_TOTAL (GEMMB * 17)        // 13294 combined blocks: 782 gemm + 12512 agg
#define NSB ((NN + 255) / 256)       // 391 scan blocks

// ---------------- device scratch (no allocations allowed) ----------------
__device__ float g_hA[NN * D];
__device__ float g_hB[NN * D];
__device__ float g_agg[NN * D];
__device__ float g_invdeg[NN];
__device__ int   g_deg[NN];
__device__ int   g_rowstart[NN + 1];
__device__ int   g_cursor[NN];
__device__ int   g_csr[EE];
__device__ int   g_is64;
__device__ double g_sum[D];
__device__ double g_sumsq[D];
__device__ int g_bsum[NSB];

__device__ __forceinline__ const float* selbuf(int sel, const float* x) {
    return sel == 0 ? x : (sel == 1 ? (const float*)g_hA : (const float*)g_hB);
}

// ---------------- packed fp32x2 helpers (Blackwell FFMA2) ----------------
__device__ __forceinline__ unsigned long long fma2(unsigned long long a,
                                                   unsigned long long b,
                                                   unsigned long long c) {
    unsigned long long d;
    asm("fma.rn.f32x2 %0, %1, %2, %3;" : "=l"(d) : "l"(a), "l"(b), "l"(c));
    return d;
}
__device__ __forceinline__ unsigned long long pack2(float x) {
    unsigned long long d;
    asm("mov.b64 %0, {%1, %1};" : "=l"(d) : "f"(x));
    return d;
}
__device__ __forceinline__ void unpack2(unsigned long long v, float& lo, float& hi) {
    asm("mov.b64 {%0, %1}, %2;" : "=f"(lo), "=f"(hi) : "l"(v));
}

// -------- prologue: fused dtype-detect (block 0) + deg/cursor init --------
__global__ void k_detect_init(const void* __restrict__ ei) {
    int i = blockIdx.x * 256 + threadIdx.x;
    if (i < NN) { g_deg[i] = 0; g_cursor[i] = 0; }
    if (blockIdx.x == 0) {
        __shared__ int bad;
        if (threadIdx.x == 0) bad = 0;
        __syncthreads();
        const long long* p = (const long long*)ei;
        int b = 0;
#pragma unroll
        for (int j = 0; j < 4; j++) {
            long long v = p[threadIdx.x * 4 + j];
            if (v < 0 || v >= NN) b = 1;
        }
        if (b) atomicOr(&bad, 1);
        __syncthreads();
        if (threadIdx.x == 0) g_is64 = !bad;
    }
}

__global__ void k_count(const void* __restrict__ ei) {
    int e = blockIdx.x * blockDim.x + threadIdx.x;
    if (e >= EE) return;
    int dst = g_is64 ? (int)((const long long*)ei)[EE + e]
                     : ((const int*)ei)[EE + e];
    atomicAdd(&g_deg[dst], 1);
}

// ---------------- 3-kernel parallel prefix sum ----------------------------
__global__ void __launch_bounds__(256) k_scan1() {
    __shared__ int s[256];
    int i = blockIdx.x * 256 + threadIdx.x;
    s[threadIdx.x] = (i < NN) ? g_deg[i] : 0;
    __syncthreads();
    for (int o = 128; o > 0; o >>= 1) {
        if (threadIdx.x < o) s[threadIdx.x] += s[threadIdx.x + o];
        __syncthreads();
    }
    if (threadIdx.x == 0) g_bsum[blockIdx.x] = s[0];
}

__global__ void __launch_bounds__(512) k_scan2() {
    __shared__ int s[512];
    int t = threadIdx.x;
    s[t] = (t < NSB) ? g_bsum[t] : 0;
    __syncthreads();
    for (int o = 1; o < 512; o <<= 1) {
        int v = (t >= o) ? s[t - o] : 0;
        __syncthreads();
        s[t] += v;
        __syncthreads();
    }
    if (t < NSB) g_bsum[t] = s[t];  // inclusive block sums
}

__global__ void __launch_bounds__(256) k_scan3() {
    __shared__ int s[256];
    int t = threadIdx.x;
    int i = blockIdx.x * 256 + t;
    int d = (i < NN) ? g_deg[i] : 0;
    s[t] = d;
    __syncthreads();
    for (int o = 1; o < 256; o <<= 1) {
        int v = (t >= o) ? s[t - o] : 0;
        __syncthreads();
        s[t] += v;
        __syncthreads();
    }
    int base = (blockIdx.x > 0) ? g_bsum[blockIdx.x - 1] : 0;
    if (i < NN) {
        g_rowstart[i] = base + s[t] - d;
        g_invdeg[i] = 1.0f / (float)(d > 1 ? d : 1);
    }
    if (i == NN - 1) g_rowstart[NN] = base + s[t];
}

__global__ void k_fill(const void* __restrict__ ei) {
    int e = blockIdx.x * blockDim.x + threadIdx.x;
    if (e >= EE) return;
    int src, dst;
    if (g_is64) {
        src = (int)((const long long*)ei)[e];
        dst = (int)((const long long*)ei)[EE + e];
    } else {
        src = ((const int*)ei)[e];
        dst = ((const int*)ei)[EE + e];
    }
    int p = atomicAdd(&g_cursor[dst], 1);
    g_csr[g_rowstart[dst] + p] = src;
}

// ===== combined kernel: block-role specialization ==========================
// Every 17th block: GEMM-r tile (Out = H @ Wr + bias).  Others: CSR gather
// (g_agg = mean of neighbor rows of H).  Both are independent of each other;
// mem-bound and fma-bound blocks coexist per SM and overlap pipes.
__global__ void __launch_bounds__(256, 2) k_aggr(
    const float* __restrict__ x, int selH, int selOut,
    const float* __restrict__ Wr, const float* __restrict__ bl)
{
    __shared__ __align__(16) float sH[BK][BMP];
    __shared__ __align__(16) float sWr[BK][D];

    int tid = threadIdx.x;
    // zero BN accumulators for the upcoming gemm_l (stats consumed by prev k_norm)
    if (blockIdx.x == 0 && tid < D) {
        g_sum[tid] = 0.0;
        g_sumsq[tid] = 0.0;
    }
    const float* __restrict__ H = selbuf(selH, x);

    if (blockIdx.x % 17 == 0) {
        // -------------------- GEMM-r role --------------------
        float* __restrict__ Out = (selOut == 1) ? (float*)g_hA : (float*)g_hB;
        int row0 = (blockIdx.x / 17) * BM;
        int ty = tid >> 4;
        int tx = tid & 15;

        unsigned long long acc[4][8];
#pragma unroll
        for (int rp = 0; rp < 4; rp++)
#pragma unroll
            for (int c = 0; c < 8; c++) acc[rp][c] = 0ULL;

        for (int kb = 0; kb < D; kb += BK) {
            __syncthreads();
#pragma unroll
            for (int it = 0; it < 2; it++) {
                int idx = tid + it * 256;
                int r = idx >> 2;
                int kq = idx & 3;
                int grow = row0 + r;
                float4 vh = {0.f, 0.f, 0.f, 0.f};
                if (grow < NN)
                    vh = *(const float4*)(H + (size_t)grow * D + kb + kq * 4);
                sH[kq * 4 + 0][r] = vh.x; sH[kq * 4 + 1][r] = vh.y;
                sH[kq * 4 + 2][r] = vh.z; sH[kq * 4 + 3][r] = vh.w;
            }
#pragma unroll
            for (int it = 0; it < 2; it++) {
                int idx = tid + it * 256;
                int k = idx >> 5;
                int cq = idx & 31;
                *(float4*)&sWr[k][cq * 4] = *(const float4*)(Wr + (size_t)(kb + k) * D + cq * 4);
            }
            __syncthreads();

#pragma unroll
            for (int k = 0; k < BK; k++) {
                unsigned long long aH[4];
#pragma unroll
                for (int rp = 0; rp < 4; rp++)
                    aH[rp] = *(const unsigned long long*)&sH[k][ty * 8 + rp * 2];
#pragma unroll
                for (int c = 0; c < 8; c++) {
                    unsigned long long wr2 = pack2(sWr[k][tx + 16 * c]);
#pragma unroll
                    for (int rp = 0; rp < 4; rp++)
                        acc[rp][c] = fma2(aH[rp], wr2, acc[rp][c]);
                }
            }
        }

        float blv[8];
#pragma unroll
        for (int c = 0; c < 8; c++) blv[c] = bl[tx + 16 * c];
#pragma unroll
        for (int rp = 0; rp < 4; rp++) {
            int r = row0 + ty * 8 + rp * 2;
            float lo[8], hi[8];
#pragma unroll
            for (int c = 0; c < 8; c++) unpack2(acc[rp][c], lo[c], hi[c]);
            if (r < NN) {
#pragma unroll
                for (int c = 0; c < 8; c++)
                    Out[(size_t)r * D + tx + 16 * c] = lo[c] + blv[c];
            }
            if (r + 1 < NN) {
#pragma unroll
                for (int c = 0; c < 8; c++)
                    Out[(size_t)(r + 1) * D + tx + 16 * c] = hi[c] + blv[c];
            }
        }
    } else {
        // -------------------- aggregation role --------------------
        int agg_idx = blockIdx.x - blockIdx.x / 17 - 1;
        int gw = agg_idx * 8 + (tid >> 5);
        int lane = tid & 31;
        if (gw >= NN) return;
        int s = g_rowstart[gw];
        int e = g_rowstart[gw + 1];
        const float* hb = H + lane * 4;
        float4 a0 = {0.f, 0.f, 0.f, 0.f};
        float4 a1 = {0.f, 0.f, 0.f, 0.f};
        int j = s;
        for (; j + 3 < e; j += 4) {
            int s0 = g_csr[j], s1 = g_csr[j + 1], s2 = g_csr[j + 2], s3 = g_csr[j + 3];
            float4 v0 = *(const float4*)(hb + (size_t)s0 * D);
            float4 v1 = *(const float4*)(hb + (size_t)s1 * D);
            float4 v2 = *(const float4*)(hb + (size_t)s2 * D);
            float4 v3 = *(const float4*)(hb + (size_t)s3 * D);
            a0.x += v0.x; a0.y += v0.y; a0.z += v0.z; a0.w += v0.w;
            a1.x += v1.x; a1.y += v1.y; a1.z += v1.z; a1.w += v1.w;
            a0.x += v2.x; a0.y += v2.y; a0.z += v2.z; a0.w += v2.w;
            a1.x += v3.x; a1.y += v3.y; a1.z += v3.z; a1.w += v3.w;
        }
        for (; j < e; j++) {
            int s0 = g_csr[j];
            float4 v0 = *(const float4*)(hb + (size_t)s0 * D);
            a0.x += v0.x; a0.y += v0.y; a0.z += v0.z; a0.w += v0.w;
        }
        float id = g_invdeg[gw];
        float4 r;
        r.x = (a0.x + a1.x) * id;
        r.y = (a0.y + a1.y) * id;
        r.z = (a0.z + a1.z) * id;
        r.w = (a0.w + a1.w) * id;
        *(float4*)(g_agg + (size_t)gw * D + lane * 4) = r;
    }
}

// ===== gemm_l: Out += agg @ Wl ; accumulate BN stats on final values ======
__global__ void __launch_bounds__(256, 2) k_gemm_l(
    int selOut, const float* __restrict__ Wl)
{
    __shared__ __align__(16) float sA[BK][BMP];
    __shared__ __align__(16) float sWl[BK][D];
    __shared__ float cs[D];
    __shared__ float csq[D];

    const float* __restrict__ A = (const float*)g_agg;
    float* __restrict__ Out = (selOut == 1) ? (float*)g_hA : (float*)g_hB;

    int tid = threadIdx.x;
    if (tid < D) { cs[tid] = 0.f; csq[tid] = 0.f; }
    int row0 = blockIdx.x * BM;
    int ty = tid >> 4;
    int tx = tid & 15;

    unsigned long long acc[4][8];
#pragma unroll
    for (int rp = 0; rp < 4; rp++)
#pragma unroll
        for (int c = 0; c < 8; c++) acc[rp][c] = 0ULL;

    for (int kb = 0; kb < D; kb += BK) {
        __syncthreads();
#pragma unroll
        for (int it = 0; it < 2; it++) {
            int idx = tid + it * 256;
            int r = idx >> 2;
            int kq = idx & 3;
            int grow = row0 + r;
            float4 va = {0.f, 0.f, 0.f, 0.f};
            if (grow < NN)
                va = *(const float4*)(A + (size_t)grow * D + kb + kq * 4);
            sA[kq * 4 + 0][r] = va.x; sA[kq * 4 + 1][r] = va.y;
            sA[kq * 4 + 2][r] = va.z; sA[kq * 4 + 3][r] = va.w;
        }
#pragma unroll
        for (int it = 0; it < 2; it++) {
            int idx = tid + it * 256;
            int k = idx >> 5;
            int cq = idx & 31;
            *(float4*)&sWl[k][cq * 4] = *(const float4*)(Wl + (size_t)(kb + k) * D + cq * 4);
        }
        __syncthreads();

#pragma unroll
        for (int k = 0; k < BK; k++) {
            unsigned long long aA[4];
#pragma unroll
            for (int rp = 0; rp < 4; rp++)
                aA[rp] = *(const unsigned long long*)&sA[k][ty * 8 + rp * 2];
#pragma unroll
            for (int c = 0; c < 8; c++) {
                unsigned long long wl2 = pack2(sWl[k][tx + 16 * c]);
#pragma unroll
                for (int rp = 0; rp < 4; rp++)
                    acc[rp][c] = fma2(aA[rp], wl2, acc[rp][c]);
            }
        }
    }

    // epilogue: Out += acc (Out already holds H@Wr + bias); BN stats on result
    float lsum[8], lsq[8];
#pragma unroll
    for (int c = 0; c < 8; c++) { lsum[c] = 0.f; lsq[c] = 0.f; }
#pragma unroll
    for (int rp = 0; rp < 4; rp++) {
        int r = row0 + ty * 8 + rp * 2;
        float lo[8], hi[8];
#pragma unroll
        for (int c = 0; c < 8; c++) unpack2(acc[rp][c], lo[c], hi[c]);
        if (r < NN) {
#pragma unroll
            for (int c = 0; c < 8; c++) {
                float v = Out[(size_t)r * D + tx + 16 * c] + lo[c];
                Out[(size_t)r * D + tx + 16 * c] = v;
                lsum[c] += v;
                lsq[c] += v * v;
            }
        }
        if (r + 1 < NN) {
#pragma unroll
            for (int c = 0; c < 8; c++) {
                float v = Out[(size_t)(r + 1) * D + tx + 16 * c] + hi[c];
                Out[(size_t)(r + 1) * D + tx + 16 * c] = v;
                lsum[c] += v;
                lsq[c] += v * v;
            }
        }
    }
#pragma unroll
    for (int c = 0; c < 8; c++) {
        atomicAdd(&cs[tx + 16 * c], lsum[c]);
        atomicAdd(&csq[tx + 16 * c], lsq[c]);
    }
    __syncthreads();
    if (tid < D) {
        atomicAdd(&g_sum[tid], (double)cs[tid]);
        atomicAdd(&g_sumsq[tid], (double)csq[tid]);
    }
}

// ---------------- BN finalize + normalize + ReLU (in place) ---------------
__global__ void __launch_bounds__(256) k_norm(int sel,
                                              const float* __restrict__ gamma,
                                              const float* __restrict__ beta) {
    float* __restrict__ h = (sel == 1) ? (float*)g_hA : (float*)g_hB;
    int lane = threadIdx.x & 31;
    int wid = threadIdx.x >> 5;
    int c0 = lane * 4;
    const double invN = 1.0 / (double)NN;
    float sc[4], sh[4];
#pragma unroll
    for (int j = 0; j < 4; j++) {
        int c = c0 + j;
        double m = g_sum[c] * invN;
        double v = g_sumsq[c] * invN - m * m;
        float is = (float)rsqrt(v + BN_EPS);
        float g = gamma[c];
        sc[j] = is * g;
        sh[j] = beta[c] - (float)m * is * g;
    }
    for (int r = blockIdx.x * 8 + wid; r < NN; r += gridDim.x * 8) {
        float4 v = *(const float4*)(h + (size_t)r * D + c0);
        v.x = fmaxf(fmaf(v.x, sc[0], sh[0]), 0.f);
        v.y = fmaxf(fmaf(v.y, sc[1], sh[1]), 0.f);
        v.z = fmaxf(fmaf(v.z, sc[2], sh[2]), 0.f);
        v.w = fmaxf(fmaf(v.w, sc[3], sh[3]), 0.f);
        *(float4*)(h + (size_t)r * D + c0) = v;
    }
}

// ---------------- output projection: out = h @ W_o + b_o ------------------
__global__ void __launch_bounds__(256) k_out(int sel, const float* __restrict__ x,
                                             const float* __restrict__ Wo,
                                             const float* __restrict__ bo,
                                             float* __restrict__ Out) {
    __shared__ __align__(16) float sHt[BK][BMP];
    __shared__ __align__(16) float sW[BK][DOUT];
    const float* __restrict__ H = selbuf(sel, x);
    int tid = threadIdx.x;
    int row0 = blockIdx.x * BM;
    int ty = tid >> 4;
    int tx = tid & 15;

    float acc[8][4];
#pragma unroll
    for (int i = 0; i < 8; i++)
#pragma unroll
        for (int j = 0; j < 4; j++) acc[i][j] = 0.f;

    for (int kb = 0; kb < D; kb += BK) {
        __syncthreads();
#pragma unroll
        for (int it = 0; it < 2; it++) {
            int idx = tid + it * 256;
            int r = idx >> 2;
            int kq = idx & 3;
            int grow = row0 + r;
            float4 vh = {0.f, 0.f, 0.f, 0.f};
            if (grow < NN)
                vh = *(const float4*)(H + (size_t)grow * D + kb + kq * 4);
            sHt[kq * 4 + 0][r] = vh.x; sHt[kq * 4 + 1][r] = vh.y;
            sHt[kq * 4 + 2][r] = vh.z; sHt[kq * 4 + 3][r] = vh.w;
        }
        {
            int k = tid >> 4;
            int cq = tid & 15;
            *(float4*)&sW[k][cq * 4] = *(const float4*)(Wo + (size_t)(kb + k) * DOUT + cq * 4);
        }
        __syncthreads();
#pragma unroll
        for (int k = 0; k < BK; k++) {
            float a[8], w[4];
#pragma unroll
            for (int i = 0; i < 8; i++) a[i] = sHt[k][ty * 8 + i];
#pragma unroll
            for (int j = 0; j < 4; j++) w[j] = sW[k][tx * 4 + j];
#pragma unroll
            for (int i = 0; i < 8; i++)
#pragma unroll
                for (int j = 0; j < 4; j++) acc[i][j] = fmaf(a[i], w[j], acc[i][j]);
        }
    }
    float b4[4];
#pragma unroll
    for (int j = 0; j < 4; j++) b4[j] = bo[tx * 4 + j];
#pragma unroll
    for (int i = 0; i < 8; i++) {
        int r = row0 + ty * 8 + i;
        if (r < NN) {
            float4 v;
            v.x = acc[i][0] + b4[0];
            v.y = acc[i][1] + b4[1];
            v.z = acc[i][2] + b4[2];
            v.w = acc[i][3] + b4[3];
            *(float4*)(Out + (size_t)r * DOUT + tx * 4) = v;
        }
    }
}

// ---------------- launch ----------------
extern "C" void kernel_launch(void* const* d_in, const int* in_sizes, int n_in,
                              void* d_out, int out_size) {
    const float* x     = (const float*)d_in[0];
    const void*  ei    = d_in[1];           // int32 or int64, detected on device
    const float* Wl    = (const float*)d_in[2];
    const float* bl    = (const float*)d_in[3];
    const float* Wr    = (const float*)d_in[4];
    const float* gamma = (const float*)d_in[5];
    const float* beta  = (const float*)d_in[6];
    const float* Wo    = (const float*)d_in[7];
    const float* bo    = (const float*)d_in[8];
    float* out = (float*)d_out;

    (void)in_sizes; (void)n_in; (void)out_size;

    k_detect_init<<<NSB, 256>>>(ei);
    k_count<<<(EE + 255) / 256, 256>>>(ei);
    k_scan1<<<NSB, 256>>>();
    k_scan2<<<1, 512>>>();
    k_scan3<<<NSB, 256>>>();
    k_fill<<<(EE + 255) / 256, 256>>>(ei);

    for (int l = 0; l < NL; l++) {
        int selIn  = (l == 0) ? 0 : ((l % 2 == 1) ? 1 : 2);
        int selOut = (l % 2 == 0) ? 1 : 2;
        k_aggr<<<TB_TOTAL, 256>>>(x, selIn, selOut,
                                  Wr + (size_t)l * D * D, bl + (size_t)l * D);
        k_gemm_l<<<GEMMB, 256>>>(selOut, Wl + (size_t)l * D * D);
        k_norm<<<2000, 256>>>(selOut, gamma + (size_t)l * D, beta + (size_t)l * D);
    }
    // after 5 layers the result lives in g_hA (sel=1)
    k_out<<<GEMMB, 256>>>(1, x, Wo, bo, out);
}

// round 16
// speedup vs baseline: 1.0124x; 1.0124x over previous
#include <cuda_runtime.h>
#include <cstdint>

#define NN 100000
#define EE 1600000
#define D 128
#define DOUT 64
#define NL 5
#define BN_EPS 1e-5

#define BM 128
#define BK 16
#define BMP 130                      // pad: conflict-free transposed STS, b64-aligned row pairs
#define GEMMB ((NN + BM - 1) / BM)   // 782 gemm tiles
#define TB_TOTAL (GEMMB * 17)        // 13294 combined blocks: 782 gemm + 12512 agg
#define NSB ((NN + 255) / 256)       // 391 scan blocks

// ---------------- device scratch (no allocations allowed) ----------------
__device__ float g_hA[NN * D];
__device__ float g_hB[NN * D];
__device__ float g_agg[NN * D];
__device__ float g_invdeg[NN];
__device__ int   g_deg[NN];
__device__ int   g_rowstart[NN + 1];
__device__ int   g_cursor[NN];
__device__ int   g_csr[EE];
__device__ int   g_is64;
__device__ double g_sum[D];
__device__ double g_sumsq[D];
__device__ int g_bsum[NSB];

__device__ __forceinline__ const float* selbuf(int sel, const float* x) {
    return sel == 0 ? x : (sel == 1 ? (const float*)g_hA : (const float*)g_hB);
}

// ---------------- packed fp32x2 helpers (Blackwell FFMA2) ----------------
__device__ __forceinline__ unsigned long long fma2(unsigned long long a,
                                                   unsigned long long b,
                                                   unsigned long long c) {
    unsigned long long d;
    asm("fma.rn.f32x2 %0, %1, %2, %3;" : "=l"(d) : "l"(a), "l"(b), "l"(c));
    return d;
}
__device__ __forceinline__ unsigned long long pack2(float x) {
    unsigned long long d;
    asm("mov.b64 %0, {%1, %1};" : "=l"(d) : "f"(x));
    return d;
}
__device__ __forceinline__ void unpack2(unsigned long long v, float& lo, float& hi) {
    asm("mov.b64 {%0, %1}, %2;" : "=f"(lo), "=f"(hi) : "l"(v));
}

// -------- prologue: fused dtype-detect (block 0) + deg/cursor init --------
__global__ void k_detect_init(const void* __restrict__ ei) {
    int i = blockIdx.x * 256 + threadIdx.x;
    if (i < NN) { g_deg[i] = 0; g_cursor[i] = 0; }
    if (blockIdx.x == 0) {
        __shared__ int bad;
        if (threadIdx.x == 0) bad = 0;
        __syncthreads();
        const long long* p = (const long long*)ei;
        int b = 0;
#pragma unroll
        for (int j = 0; j < 4; j++) {
            long long v = p[threadIdx.x * 4 + j];
            if (v < 0 || v >= NN) b = 1;
        }
        if (b) atomicOr(&bad, 1);
        __syncthreads();
        if (threadIdx.x == 0) g_is64 = !bad;
    }
}

__global__ void k_count(const void* __restrict__ ei) {
    int e = blockIdx.x * blockDim.x + threadIdx.x;
    if (e >= EE) return;
    int dst = g_is64 ? (int)((const long long*)ei)[EE + e]
                     : ((const int*)ei)[EE + e];
    atomicAdd(&g_deg[dst], 1);
}

// ---------------- 3-kernel parallel prefix sum ----------------------------
__global__ void __launch_bounds__(256) k_scan1() {
    __shared__ int s[256];
    int i = blockIdx.x * 256 + threadIdx.x;
    s[threadIdx.x] = (i < NN) ? g_deg[i] : 0;
    __syncthreads();
    for (int o = 128; o > 0; o >>= 1) {
        if (threadIdx.x < o) s[threadIdx.x] += s[threadIdx.x + o];
        __syncthreads();
    }
    if (threadIdx.x == 0) g_bsum[blockIdx.x] = s[0];
}

__global__ void __launch_bounds__(512) k_scan2() {
    __shared__ int s[512];
    int t = threadIdx.x;
    s[t] = (t < NSB) ? g_bsum[t] : 0;
    __syncthreads();
    for (int o = 1; o < 512; o <<= 1) {
        int v = (t >= o) ? s[t - o] : 0;
        __syncthreads();
        s[t] += v;
        __syncthreads();
    }
    if (t < NSB) g_bsum[t] = s[t];  // inclusive block sums
}

__global__ void __launch_bounds__(256) k_scan3() {
    __shared__ int s[256];
    int t = threadIdx.x;
    int i = blockIdx.x * 256 + t;
    int d = (i < NN) ? g_deg[i] : 0;
    s[t] = d;
    __syncthreads();
    for (int o = 1; o < 256; o <<= 1) {
        int v = (t >= o) ? s[t - o] : 0;
        __syncthreads();
        s[t] += v;
        __syncthreads();
    }
    int base = (blockIdx.x > 0) ? g_bsum[blockIdx.x - 1] : 0;
    if (i < NN) {
        g_rowstart[i] = base + s[t] - d;
        g_invdeg[i] = 1.0f / (float)(d > 1 ? d : 1);
    }
    if (i == NN - 1) g_rowstart[NN] = base + s[t];
}

__global__ void k_fill(const void* __restrict__ ei) {
    int e = blockIdx.x * blockDim.x + threadIdx.x;
    if (e >= EE) return;
    int src, dst;
    if (g_is64) {
        src = (int)((const long long*)ei)[e];
        dst = (int)((const long long*)ei)[EE + e];
    } else {
        src = ((const int*)ei)[e];
        dst = ((const int*)ei)[EE + e];
    }
    int p = atomicAdd(&g_cursor[dst], 1);
    g_csr[g_rowstart[dst] + p] = src;
}

// ===== combined kernel: block-role specialization ==========================
// Every 17th block: GEMM-r tile (Out = H @ Wr + bias).  Others: CSR gather
// (g_agg = mean of neighbor rows of H).  Both are independent of each other;
// mem-bound and fma-bound blocks coexist per SM and overlap pipes.
__global__ void __launch_bounds__(256, 2) k_aggr(
    const float* __restrict__ x, int selH, int selOut,
    const float* __restrict__ Wr, const float* __restrict__ bl)
{
    __shared__ __align__(16) float sH[BK][BMP];
    __shared__ __align__(16) float sWr[BK][D];

    int tid = threadIdx.x;
    // zero BN accumulators for the upcoming gemm_l (stats consumed by prev k_norm)
    if (blockIdx.x == 0 && tid < D) {
        g_sum[tid] = 0.0;
        g_sumsq[tid] = 0.0;
    }
    const float* __restrict__ H = selbuf(selH, x);

    if (blockIdx.x % 17 == 0) {
        // -------------------- GEMM-r role --------------------
        float* __restrict__ Out = (selOut == 1) ? (float*)g_hA : (float*)g_hB;
        int row0 = (blockIdx.x / 17) * BM;
        int ty = tid >> 4;
        int tx = tid & 15;

        unsigned long long acc[4][8];
#pragma unroll
        for (int rp = 0; rp < 4; rp++)
#pragma unroll
            for (int c = 0; c < 8; c++) acc[rp][c] = 0ULL;

        for (int kb = 0; kb < D; kb += BK) {
            __syncthreads();
#pragma unroll
            for (int it = 0; it < 2; it++) {
                int idx = tid + it * 256;
                int r = idx >> 2;
                int kq = idx & 3;
                int grow = row0 + r;
                float4 vh = {0.f, 0.f, 0.f, 0.f};
                if (grow < NN)
                    vh = *(const float4*)(H + (size_t)grow * D + kb + kq * 4);
                sH[kq * 4 + 0][r] = vh.x; sH[kq * 4 + 1][r] = vh.y;
                sH[kq * 4 + 2][r] = vh.z; sH[kq * 4 + 3][r] = vh.w;
            }
#pragma unroll
            for (int it = 0; it < 2; it++) {
                int idx = tid + it * 256;
                int k = idx >> 5;
                int cq = idx & 31;
                *(float4*)&sWr[k][cq * 4] = *(const float4*)(Wr + (size_t)(kb + k) * D + cq * 4);
            }
            __syncthreads();

#pragma unroll
            for (int k = 0; k < BK; k++) {
                unsigned long long aH[4];
#pragma unroll
                for (int rp = 0; rp < 4; rp++)
                    aH[rp] = *(const unsigned long long*)&sH[k][ty * 8 + rp * 2];
#pragma unroll
                for (int c = 0; c < 8; c++) {
                    unsigned long long wr2 = pack2(sWr[k][tx + 16 * c]);
#pragma unroll
                    for (int rp = 0; rp < 4; rp++)
                        acc[rp][c] = fma2(aH[rp], wr2, acc[rp][c]);
                }
            }
        }

        float blv[8];
#pragma unroll
        for (int c = 0; c < 8; c++) blv[c] = bl[tx + 16 * c];
#pragma unroll
        for (int rp = 0; rp < 4; rp++) {
            int r = row0 + ty * 8 + rp * 2;
            float lo[8], hi[8];
#pragma unroll
            for (int c = 0; c < 8; c++) unpack2(acc[rp][c], lo[c], hi[c]);
            if (r < NN) {
#pragma unroll
                for (int c = 0; c < 8; c++)
                    Out[(size_t)r * D + tx + 16 * c] = lo[c] + blv[c];
            }
            if (r + 1 < NN) {
#pragma unroll
                for (int c = 0; c < 8; c++)
                    Out[(size_t)(r + 1) * D + tx + 16 * c] = hi[c] + blv[c];
            }
        }
    } else {
        // -------------------- aggregation role --------------------
        int agg_idx = blockIdx.x - blockIdx.x / 17 - 1;
        int gw = agg_idx * 8 + (tid >> 5);
        int lane = tid & 31;
        if (gw >= NN) return;
        int s = g_rowstart[gw];
        int e = g_rowstart[gw + 1];
        const float* hb = H + lane * 4;
        float4 a0 = {0.f, 0.f, 0.f, 0.f};
        float4 a1 = {0.f, 0.f, 0.f, 0.f};
        int j = s;
        for (; j + 3 < e; j += 4) {
            int s0 = g_csr[j], s1 = g_csr[j + 1], s2 = g_csr[j + 2], s3 = g_csr[j + 3];
            float4 v0 = *(const float4*)(hb + (size_t)s0 * D);
            float4 v1 = *(const float4*)(hb + (size_t)s1 * D);
            float4 v2 = *(const float4*)(hb + (size_t)s2 * D);
            float4 v3 = *(const float4*)(hb + (size_t)s3 * D);
            a0.x += v0.x; a0.y += v0.y; a0.z += v0.z; a0.w += v0.w;
            a1.x += v1.x; a1.y += v1.y; a1.z += v1.z; a1.w += v1.w;
            a0.x += v2.x; a0.y += v2.y; a0.z += v2.z; a0.w += v2.w;
            a1.x += v3.x; a1.y += v3.y; a1.z += v3.z; a1.w += v3.w;
        }
        for (; j < e; j++) {
            int s0 = g_csr[j];
            float4 v0 = *(const float4*)(hb + (size_t)s0 * D);
            a0.x += v0.x; a0.y += v0.y; a0.z += v0.z; a0.w += v0.w;
        }
        float id = g_invdeg[gw];
        float4 r;
        r.x = (a0.x + a1.x) * id;
        r.y = (a0.y + a1.y) * id;
        r.z = (a0.z + a1.z) * id;
        r.w = (a0.w + a1.w) * id;
        *(float4*)(g_agg + (size_t)gw * D + lane * 4) = r;
    }
}

// ===== gemm_l: Out += agg @ Wl ; accumulate BN stats on final values ======
__global__ void __launch_bounds__(256, 2) k_gemm_l(
    int selOut, const float* __restrict__ Wl)
{
    __shared__ __align__(16) float sA[BK][BMP];
    __shared__ __align__(16) float sWl[BK][D];
    __shared__ float cs[D];
    __shared__ float csq[D];

    const float* __restrict__ A = (const float*)g_agg;
    float* __restrict__ Out = (selOut == 1) ? (float*)g_hA : (float*)g_hB;

    int tid = threadIdx.x;
    if (tid < D) { cs[tid] = 0.f; csq[tid] = 0.f; }
    int row0 = blockIdx.x * BM;
    int ty = tid >> 4;
    int tx = tid & 15;

    unsigned long long acc[4][8];
#pragma unroll
    for (int rp = 0; rp < 4; rp++)
#pragma unroll
        for (int c = 0; c < 8; c++) acc[rp][c] = 0ULL;

    for (int kb = 0; kb < D; kb += BK) {
        __syncthreads();
#pragma unroll
        for (int it = 0; it < 2; it++) {
            int idx = tid + it * 256;
            int r = idx >> 2;
            int kq = idx & 3;
            int grow = row0 + r;
            float4 va = {0.f, 0.f, 0.f, 0.f};
            if (grow < NN)
                va = *(const float4*)(A + (size_t)grow * D + kb + kq * 4);
            sA[kq * 4 + 0][r] = va.x; sA[kq * 4 + 1][r] = va.y;
            sA[kq * 4 + 2][r] = va.z; sA[kq * 4 + 3][r] = va.w;
        }
#pragma unroll
        for (int it = 0; it < 2; it++) {
            int idx = tid + it * 256;
            int k = idx >> 5;
            int cq = idx & 31;
            *(float4*)&sWl[k][cq * 4] = *(const float4*)(Wl + (size_t)(kb + k) * D + cq * 4);
        }
        __syncthreads();

#pragma unroll
        for (int k = 0; k < BK; k++) {
            unsigned long long aA[4];
#pragma unroll
            for (int rp = 0; rp < 4; rp++)
                aA[rp] = *(const unsigned long long*)&sA[k][ty * 8 + rp * 2];
#pragma unroll
            for (int c = 0; c < 8; c++) {
                unsigned long long wl2 = pack2(sWl[k][tx + 16 * c]);
#pragma unroll
                for (int rp = 0; rp < 4; rp++)
                    acc[rp][c] = fma2(aA[rp], wl2, acc[rp][c]);
            }
        }
    }

    // epilogue: Out += acc (Out already holds H@Wr + bias); BN stats on result
    float lsum[8], lsq[8];
#pragma unroll
    for (int c = 0; c < 8; c++) { lsum[c] = 0.f; lsq[c] = 0.f; }
#pragma unroll
    for (int rp = 0; rp < 4; rp++) {
        int r = row0 + ty * 8 + rp * 2;
        float lo[8], hi[8];
#pragma unroll
        for (int c = 0; c < 8; c++) unpack2(acc[rp][c], lo[c], hi[c]);
        if (r < NN) {
#pragma unroll
            for (int c = 0; c < 8; c++) {
                float v = Out[(size_t)r * D + tx + 16 * c] + lo[c];
                Out[(size_t)r * D + tx + 16 * c] = v;
                lsum[c] += v;
                lsq[c] += v * v;
            }
        }
        if (r + 1 < NN) {
#pragma unroll
            for (int c = 0; c < 8; c++) {
                float v = Out[(size_t)(r + 1) * D + tx + 16 * c] + hi[c];
                Out[(size_t)(r + 1) * D + tx + 16 * c] = v;
                lsum[c] += v;
                lsq[c] += v * v;
            }
        }
    }
#pragma unroll
    for (int c = 0; c < 8; c++) {
        atomicAdd(&cs[tx + 16 * c], lsum[c]);
        atomicAdd(&csq[tx + 16 * c], lsq[c]);
    }
    __syncthreads();
    if (tid < D) {
        atomicAdd(&g_sum[tid], (double)cs[tid]);
        atomicAdd(&g_sumsq[tid], (double)csq[tid]);
    }
}

// ---------------- BN finalize + normalize + ReLU (in place) ---------------
__global__ void __launch_bounds__(256) k_norm(int sel,
                                              const float* __restrict__ gamma,
                                              const float* __restrict__ beta) {
    float* __restrict__ h = (sel == 1) ? (float*)g_hA : (float*)g_hB;
    int lane = threadIdx.x & 31;
    int wid = threadIdx.x >> 5;
    int c0 = lane * 4;
    const double invN = 1.0 / (double)NN;
    float sc[4], sh[4];
#pragma unroll
    for (int j = 0; j < 4; j++) {
        int c = c0 + j;
        double m = g_sum[c] * invN;
        double v = g_sumsq[c] * invN - m * m;
        float is = (float)rsqrt(v + BN_EPS);
        float g = gamma[c];
        sc[j] = is * g;
        sh[j] = beta[c] - (float)m * is * g;
    }
    for (int r = blockIdx.x * 8 + wid; r < NN; r += gridDim.x * 8) {
        float4 v = *(const float4*)(h + (size_t)r * D + c0);
        v.x = fmaxf(fmaf(v.x, sc[0], sh[0]), 0.f);
        v.y = fmaxf(fmaf(v.y, sc[1], sh[1]), 0.f);
        v.z = fmaxf(fmaf(v.z, sc[2], sh[2]), 0.f);
        v.w = fmaxf(fmaf(v.w, sc[3], sh[3]), 0.f);
        *(float4*)(h + (size_t)r * D + c0) = v;
    }
}

// ---------------- output projection: out = h @ W_o + b_o ------------------
__global__ void __launch_bounds__(256) k_out(int sel, const float* __restrict__ x,
                                             const float* __restrict__ Wo,
                                             const float* __restrict__ bo,
                                             float* __restrict__ Out) {
    __shared__ __align__(16) float sHt[BK][BMP];
    __shared__ __align__(16) float sW[BK][DOUT];
    const float* __restrict__ H = selbuf(sel, x);
    int tid = threadIdx.x;
    int row0 = blockIdx.x * BM;
    int ty = tid >> 4;
    int tx = tid & 15;

    float acc[8][4];
#pragma unroll
    for (int i = 0; i < 8; i++)
#pragma unroll
        for (int j = 0; j < 4; j++) acc[i][j] = 0.f;

    for (int kb = 0; kb < D; kb += BK) {
        __syncthreads();
#pragma unroll
        for (int it = 0; it < 2; it++) {
            int idx = tid + it * 256;
            int r = idx >> 2;
            int kq = idx & 3;
            int grow = row0 + r;
            float4 vh = {0.f, 0.f, 0.f, 0.f};
            if (grow < NN)
                vh = *(const float4*)(H + (size_t)grow * D + kb + kq * 4);
            sHt[kq * 4 + 0][r] = vh.x; sHt[kq * 4 + 1][r] = vh.y;
            sHt[kq * 4 + 2][r] = vh.z; sHt[kq * 4 + 3][r] = vh.w;
        }
        {
            int k = tid >> 4;
            int cq = tid & 15;
            *(float4*)&sW[k][cq * 4] = *(const float4*)(Wo + (size_t)(kb + k) * DOUT + cq * 4);
        }
        __syncthreads();
#pragma unroll
        for (int k = 0; k < BK; k++) {
            float a[8], w[4];
#pragma unroll
            for (int i = 0; i < 8; i++) a[i] = sHt[k][ty * 8 + i];
#pragma unroll
            for (int j = 0; j < 4; j++) w[j] = sW[k][tx * 4 + j];
#pragma unroll
            for (int i = 0; i < 8; i++)
#pragma unroll
                for (int j = 0; j < 4; j++) acc[i][j] = fmaf(a[i], w[j], acc[i][j]);
        }
    }
    float b4[4];
#pragma unroll
    for (int j = 0; j < 4; j++) b4[j] = bo[tx * 4 + j];
#pragma unroll
    for (int i = 0; i < 8; i++) {
        int r = row0 + ty * 8 + i;
        if (r < NN) {
            float4 v;
            v.x = acc[i][0] + b4[0];
            v.y = acc[i][1] + b4[1];
            v.z = acc[i][2] + b4[2];
            v.w = acc[i][3] + b4[3];
            *(float4*)(Out + (size_t)r * DOUT + tx * 4) = v;
        }
    }
}

// ---------------- launch ----------------
extern "C" void kernel_launch(void* const* d_in, const int* in_sizes, int n_in,
                              void* d_out, int out_size) {
    const float* x     = (const float*)d_in[0];
    const void*  ei    = d_in[1];           // int32 or int64, detected on device
    const float* Wl    = (const float*)d_in[2];
    const float* bl    = (const float*)d_in[3];
    const float* Wr    = (const float*)d_in[4];
    const float* gamma = (const float*)d_in[5];
    const float* beta  = (const float*)d_in[6];
    const float* Wo    = (const float*)d_in[7];
    const float* bo    = (const float*)d_in[8];
    float* out = (float*)d_out;

    (void)in_sizes; (void)n_in; (void)out_size;

    k_detect_init<<<NSB, 256>>>(ei);
    k_count<<<(EE + 255) / 256, 256>>>(ei);
    k_scan1<<<NSB, 256>>>();
    k_scan2<<<1, 512>>>();
    k_scan3<<<NSB, 256>>>();
    k_fill<<<(EE + 255) / 256, 256>>>(ei);

    for (int l = 0; l < NL; l++) {
        int selIn  = (l == 0) ? 0 : ((l % 2 == 1) ? 1 : 2);
        int selOut = (l % 2 == 0) ? 1 : 2;
        k_aggr<<<TB_TOTAL, 256>>>(x, selIn, selOut,
                                  Wr + (size_t)l * D * D, bl + (size_t)l * D);
        k_gemm_l<<<GEMMB, 256>>>(selOut, Wl + (size_t)l * D * D);
        k_norm<<<2000, 256>>>(selOut, gamma + (size_t)l * D, beta + (size_t)l * D);
    }
    // after 5 layers the result lives in g_hA (sel=1)
    k_out<<<GEMMB, 256>>>(1, x, Wo, bo, out);
}

// round 17
// speedup vs baseline: 1.3726x; 1.3557x over previous
#include <cuda_runtime.h>
#include <cstdint>

#define NN 100000
#define EE 1600000
#define D 128
#define DOUT 64
#define NL 5
#define BN_EPS 1e-5

#define BM 128
#define BK 16
#define BMP 130                      // pad: conflict-free transposed STS, b64-aligned row pairs
#define GEMMB ((NN + BM - 1) / BM)   // 782 gemm tiles
#define NSB ((NN + 255) / 256)       // 391 scan blocks

// ---------------- device scratch (no allocations allowed) ----------------
__device__ float g_hA[NN * D];
__device__ float g_hB[NN * D];
__device__ float g_agg[NN * D];
__device__ float g_invdeg[NN];
__device__ int   g_deg[NN];
__device__ int   g_rowstart[NN + 1];
__device__ int   g_cursor[NN];
__device__ int   g_csr[EE];
__device__ int   g_is64;
__device__ double g_sum[D];
__device__ double g_sumsq[D];
__device__ int g_bsum[NSB];

__device__ __forceinline__ const float* selbuf(int sel, const float* x) {
    return sel == 0 ? x : (sel == 1 ? (const float*)g_hA : (const float*)g_hB);
}

// ---------------- packed fp32x2 helpers (Blackwell FFMA2) ----------------
__device__ __forceinline__ unsigned long long fma2(unsigned long long a,
                                                   unsigned long long b,
                                                   unsigned long long c) {
    unsigned long long d;
    asm("fma.rn.f32x2 %0, %1, %2, %3;" : "=l"(d) : "l"(a), "l"(b), "l"(c));
    return d;
}
__device__ __forceinline__ unsigned long long pack2(float x) {
    unsigned long long d;
    asm("mov.b64 %0, {%1, %1};" : "=l"(d) : "f"(x));
    return d;
}
__device__ __forceinline__ void unpack2(unsigned long long v, float& lo, float& hi) {
    asm("mov.b64 {%0, %1}, %2;" : "=f"(lo), "=f"(hi) : "l"(v));
}

// -------- prologue: fused dtype-detect (block 0) + deg/cursor init --------
__global__ void k_detect_init(const void* __restrict__ ei) {
    int i = blockIdx.x * 256 + threadIdx.x;
    if (i < NN) { g_deg[i] = 0; g_cursor[i] = 0; }
    if (blockIdx.x == 0) {
        __shared__ int bad;
        if (threadIdx.x == 0) bad = 0;
        __syncthreads();
        const long long* p = (const long long*)ei;
        int b = 0;
#pragma unroll
        for (int j = 0; j < 4; j++) {
            long long v = p[threadIdx.x * 4 + j];
            if (v < 0 || v >= NN) b = 1;
        }
        if (b) atomicOr(&bad, 1);
        __syncthreads();
        if (threadIdx.x == 0) g_is64 = !bad;
    }
}

__global__ void k_count(const void* __restrict__ ei) {
    int e = blockIdx.x * blockDim.x + threadIdx.x;
    if (e >= EE) return;
    int dst = g_is64 ? (int)((const long long*)ei)[EE + e]
                     : ((const int*)ei)[EE + e];
    atomicAdd(&g_deg[dst], 1);
}

// ---------------- 3-kernel parallel prefix sum ----------------------------
__global__ void __launch_bounds__(256) k_scan1() {
    __shared__ int s[256];
    int i = blockIdx.x * 256 + threadIdx.x;
    s[threadIdx.x] = (i < NN) ? g_deg[i] : 0;
    __syncthreads();
    for (int o = 128; o > 0; o >>= 1) {
        if (threadIdx.x < o) s[threadIdx.x] += s[threadIdx.x + o];
        __syncthreads();
    }
    if (threadIdx.x == 0) g_bsum[blockIdx.x] = s[0];
}

__global__ void __launch_bounds__(512) k_scan2() {
    __shared__ int s[512];
    int t = threadIdx.x;
    s[t] = (t < NSB) ? g_bsum[t] : 0;
    __syncthreads();
    for (int o = 1; o < 512; o <<= 1) {
        int v = (t >= o) ? s[t - o] : 0;
        __syncthreads();
        s[t] += v;
        __syncthreads();
    }
    if (t < NSB) g_bsum[t] = s[t];  // inclusive block sums
}

__global__ void __launch_bounds__(256) k_scan3() {
    __shared__ int s[256];
    int t = threadIdx.x;
    int i = blockIdx.x * 256 + t;
    int d = (i < NN) ? g_deg[i] : 0;
    s[t] = d;
    __syncthreads();
    for (int o = 1; o < 256; o <<= 1) {
        int v = (t >= o) ? s[t - o] : 0;
        __syncthreads();
        s[t] += v;
        __syncthreads();
    }
    int base = (blockIdx.x > 0) ? g_bsum[blockIdx.x - 1] : 0;
    if (i < NN) {
        g_rowstart[i] = base + s[t] - d;
        g_invdeg[i] = 1.0f / (float)(d > 1 ? d : 1);
    }
    if (i == NN - 1) g_rowstart[NN] = base + s[t];
}

__global__ void k_fill(const void* __restrict__ ei) {
    int e = blockIdx.x * blockDim.x + threadIdx.x;
    if (e >= EE) return;
    int src, dst;
    if (g_is64) {
        src = (int)((const long long*)ei)[e];
        dst = (int)((const long long*)ei)[EE + e];
    } else {
        src = ((const int*)ei)[e];
        dst = ((const int*)ei)[EE + e];
    }
    int p = atomicAdd(&g_cursor[dst], 1);
    g_csr[g_rowstart[dst] + p] = src;
}

// ---------------- scatter-mean aggregation (CSR gather, warp/node) -------
__global__ void __launch_bounds__(256) k_agg(const float* __restrict__ x, int sel) {
    // block 0 also zeroes the BN accumulators for the upcoming GEMM
    if (blockIdx.x == 0 && threadIdx.x < D) {
        g_sum[threadIdx.x] = 0.0;
        g_sumsq[threadIdx.x] = 0.0;
    }
    const float* __restrict__ h = selbuf(sel, x);
    int gw = (blockIdx.x * 256 + threadIdx.x) >> 5;
    int lane = threadIdx.x & 31;
    if (gw >= NN) return;
    int s = g_rowstart[gw];
    int e = g_rowstart[gw + 1];
    const float* hb = h + lane * 4;
    float4 a0 = {0.f, 0.f, 0.f, 0.f};
    float4 a1 = {0.f, 0.f, 0.f, 0.f};
    int j = s;
    for (; j + 3 < e; j += 4) {
        int s0 = g_csr[j], s1 = g_csr[j + 1], s2 = g_csr[j + 2], s3 = g_csr[j + 3];
        float4 v0 = *(const float4*)(hb + (size_t)s0 * D);
        float4 v1 = *(const float4*)(hb + (size_t)s1 * D);
        float4 v2 = *(const float4*)(hb + (size_t)s2 * D);
        float4 v3 = *(const float4*)(hb + (size_t)s3 * D);
        a0.x += v0.x; a0.y += v0.y; a0.z += v0.z; a0.w += v0.w;
        a1.x += v1.x; a1.y += v1.y; a1.z += v1.z; a1.w += v1.w;
        a0.x += v2.x; a0.y += v2.y; a0.z += v2.z; a0.w += v2.w;
        a1.x += v3.x; a1.y += v3.y; a1.z += v3.z; a1.w += v3.w;
    }
    for (; j < e; j++) {
        int s0 = g_csr[j];
        float4 v0 = *(const float4*)(hb + (size_t)s0 * D);
        a0.x += v0.x; a0.y += v0.y; a0.z += v0.z; a0.w += v0.w;
    }
    float id = g_invdeg[gw];
    float4 r;
    r.x = (a0.x + a1.x) * id;
    r.y = (a0.y + a1.y) * id;
    r.z = (a0.z + a1.z) * id;
    r.w = (a0.w + a1.w) * id;
    *(float4*)(g_agg + (size_t)gw * D + lane * 4) = r;
}

// ---------------- fused dual-GEMM + bias + BN partial sums ----------------
__global__ void __launch_bounds__(256, 2) k_gemm(
    const float* __restrict__ x, int selH, int selOut,
    const float* __restrict__ Wl, const float* __restrict__ bl,
    const float* __restrict__ Wr)
{
    __shared__ __align__(16) float sA[BK][BMP];
    __shared__ __align__(16) float sH[BK][BMP];
    __shared__ __align__(16) float sWl[BK][D];
    __shared__ __align__(16) float sWr[BK][D];
    __shared__ float cs[D];
    __shared__ float csq[D];

    const float* __restrict__ A = (const float*)g_agg;
    const float* __restrict__ H = selbuf(selH, x);
    float* __restrict__ Out = (selOut == 1) ? (float*)g_hA : (float*)g_hB;

    int tid = threadIdx.x;
    if (tid < D) { cs[tid] = 0.f; csq[tid] = 0.f; }
    int row0 = blockIdx.x * BM;
    int ty = tid >> 4;   // row group 0..15 (8 rows each)
    int tx = tid & 15;   // col base; thread's cols = tx + 16*c

    unsigned long long acc[4][8];
#pragma unroll
    for (int rp = 0; rp < 4; rp++)
#pragma unroll
        for (int c = 0; c < 8; c++) acc[rp][c] = 0ULL;

    for (int kb = 0; kb < D; kb += BK) {
        __syncthreads();
        // stage A and H tiles, transposed to [k][row]
#pragma unroll
        for (int it = 0; it < 2; it++) {
            int idx = tid + it * 256;
            int r = idx >> 2;
            int kq = idx & 3;
            int grow = row0 + r;
            float4 va = {0.f, 0.f, 0.f, 0.f};
            float4 vh = {0.f, 0.f, 0.f, 0.f};
            if (grow < NN) {
                va = *(const float4*)(A + (size_t)grow * D + kb + kq * 4);
                vh = *(const float4*)(H + (size_t)grow * D + kb + kq * 4);
            }
            sA[kq * 4 + 0][r] = va.x; sA[kq * 4 + 1][r] = va.y;
            sA[kq * 4 + 2][r] = va.z; sA[kq * 4 + 3][r] = va.w;
            sH[kq * 4 + 0][r] = vh.x; sH[kq * 4 + 1][r] = vh.y;
            sH[kq * 4 + 2][r] = vh.z; sH[kq * 4 + 3][r] = vh.w;
        }
        // stage W tiles [k][col] (natural layout)
#pragma unroll
        for (int it = 0; it < 2; it++) {
            int idx = tid + it * 256;
            int k = idx >> 5;
            int cq = idx & 31;
            *(float4*)&sWl[k][cq * 4] = *(const float4*)(Wl + (size_t)(kb + k) * D + cq * 4);
            *(float4*)&sWr[k][cq * 4] = *(const float4*)(Wr + (size_t)(kb + k) * D + cq * 4);
        }
        __syncthreads();

#pragma unroll
        for (int k = 0; k < BK; k++) {
            unsigned long long aA[4], aH[4];
#pragma unroll
            for (int rp = 0; rp < 4; rp++) {
                aA[rp] = *(const unsigned long long*)&sA[k][ty * 8 + rp * 2];
                aH[rp] = *(const unsigned long long*)&sH[k][ty * 8 + rp * 2];
            }
#pragma unroll
            for (int c = 0; c < 8; c++) {
                unsigned long long wl2 = pack2(sWl[k][tx + 16 * c]);
                unsigned long long wr2 = pack2(sWr[k][tx + 16 * c]);
#pragma unroll
                for (int rp = 0; rp < 4; rp++) {
                    acc[rp][c] = fma2(aA[rp], wl2, acc[rp][c]);
                    acc[rp][c] = fma2(aH[rp], wr2, acc[rp][c]);
                }
            }
        }
    }

    // epilogue: bias add, store pre-BN activations, accumulate BN sums
    float blv[8], lsum[8], lsq[8];
#pragma unroll
    for (int c = 0; c < 8; c++) {
        blv[c] = bl[tx + 16 * c];
        lsum[c] = 0.f;
        lsq[c] = 0.f;
    }
#pragma unroll
    for (int rp = 0; rp < 4; rp++) {
        int r = row0 + ty * 8 + rp * 2;
        float lo[8], hi[8];
#pragma unroll
        for (int c = 0; c < 8; c++) {
            unpack2(acc[rp][c], lo[c], hi[c]);
            lo[c] += blv[c];
            hi[c] += blv[c];
        }
        if (r < NN) {
#pragma unroll
            for (int c = 0; c < 8; c++) {
                Out[(size_t)r * D + tx + 16 * c] = lo[c];
                lsum[c] += lo[c];
                lsq[c] += lo[c] * lo[c];
            }
        }
        if (r + 1 < NN) {
#pragma unroll
            for (int c = 0; c < 8; c++) {
                Out[(size_t)(r + 1) * D + tx + 16 * c] = hi[c];
                lsum[c] += hi[c];
                lsq[c] += hi[c] * hi[c];
            }
        }
    }
#pragma unroll
    for (int c = 0; c < 8; c++) {
        atomicAdd(&cs[tx + 16 * c], lsum[c]);
        atomicAdd(&csq[tx + 16 * c], lsq[c]);
    }
    __syncthreads();
    if (tid < D) {
        atomicAdd(&g_sum[tid], (double)cs[tid]);
        atomicAdd(&g_sumsq[tid], (double)csq[tid]);
    }
}

// ---------------- BN finalize + normalize + ReLU (in place) ---------------
__global__ void __launch_bounds__(256) k_norm(int sel,
                                              const float* __restrict__ gamma,
                                              const float* __restrict__ beta) {
    float* __restrict__ h = (sel == 1) ? (float*)g_hA : (float*)g_hB;
    int lane = threadIdx.x & 31;
    int wid = threadIdx.x >> 5;
    int c0 = lane * 4;
    const double invN = 1.0 / (double)NN;
    float sc[4], sh[4];
#pragma unroll
    for (int j = 0; j < 4; j++) {
        int c = c0 + j;
        double m = g_sum[c] * invN;
        double v = g_sumsq[c] * invN - m * m;
        float is = (float)rsqrt(v + BN_EPS);
        float g = gamma[c];
        sc[j] = is * g;
        sh[j] = beta[c] - (float)m * is * g;
    }
    for (int r = blockIdx.x * 8 + wid; r < NN; r += gridDim.x * 8) {
        float4 v = *(const float4*)(h + (size_t)r * D + c0);
        v.x = fmaxf(fmaf(v.x, sc[0], sh[0]), 0.f);
        v.y = fmaxf(fmaf(v.y, sc[1], sh[1]), 0.f);
        v.z = fmaxf(fmaf(v.z, sc[2], sh[2]), 0.f);
        v.w = fmaxf(fmaf(v.w, sc[3], sh[3]), 0.f);
        *(float4*)(h + (size_t)r * D + c0) = v;
    }
}

// ------- output projection with fused last-layer BN+ReLU ------------------
// out = relu(bn(h)) @ W_o + b_o ; h = g_hA, BN stats in g_sum/g_sumsq
__global__ void __launch_bounds__(256) k_out(
    const float* __restrict__ gamma, const float* __restrict__ beta,
    const float* __restrict__ Wo, const float* __restrict__ bo,
    float* __restrict__ Out)
{
    __shared__ __align__(16) float sHt[BK][BMP];
    __shared__ __align__(16) float sW[BK][DOUT];
    __shared__ float snc[D];
    __shared__ float snh[D];
    const float* __restrict__ H = (const float*)g_hA;
    int tid = threadIdx.x;
    if (tid < D) {
        const double invN = 1.0 / (double)NN;
        double m = g_sum[tid] * invN;
        double v = g_sumsq[tid] * invN - m * m;
        float is = (float)rsqrt(v + BN_EPS);
        float g = gamma[tid];
        snc[tid] = is * g;
        snh[tid] = beta[tid] - (float)m * is * g;
    }
    int row0 = blockIdx.x * BM;
    int ty = tid >> 4;   // 16 row groups × 8 rows
    int tx = tid & 15;   // 16 col groups × 4 cols

    float acc[8][4];
#pragma unroll
    for (int i = 0; i < 8; i++)
#pragma unroll
        for (int j = 0; j < 4; j++) acc[i][j] = 0.f;

    for (int kb = 0; kb < D; kb += BK) {
        __syncthreads();   // also covers snc/snh init on first iteration
#pragma unroll
        for (int it = 0; it < 2; it++) {
            int idx = tid + it * 256;
            int r = idx >> 2;
            int kq = idx & 3;
            int grow = row0 + r;
            float4 vh = {0.f, 0.f, 0.f, 0.f};
            if (grow < NN)
                vh = *(const float4*)(H + (size_t)grow * D + kb + kq * 4);
            int c0 = kb + kq * 4;
            vh.x = fmaxf(fmaf(vh.x, snc[c0 + 0], snh[c0 + 0]), 0.f);
            vh.y = fmaxf(fmaf(vh.y, snc[c0 + 1], snh[c0 + 1]), 0.f);
            vh.z = fmaxf(fmaf(vh.z, snc[c0 + 2], snh[c0 + 2]), 0.f);
            vh.w = fmaxf(fmaf(vh.w, snc[c0 + 3], snh[c0 + 3]), 0.f);
            sHt[kq * 4 + 0][r] = vh.x; sHt[kq * 4 + 1][r] = vh.y;
            sHt[kq * 4 + 2][r] = vh.z; sHt[kq * 4 + 3][r] = vh.w;
        }
        {
            int k = tid >> 4;
            int cq = tid & 15;
            *(float4*)&sW[k][cq * 4] = *(const float4*)(Wo + (size_t)(kb + k) * DOUT + cq * 4);
        }
        __syncthreads();
#pragma unroll
        for (int k = 0; k < BK; k++) {
            float a[8], w[4];
#pragma unroll
            for (int i = 0; i < 8; i++) a[i] = sHt[k][ty * 8 + i];
#pragma unroll
            for (int j = 0; j < 4; j++) w[j] = sW[k][tx * 4 + j];
#pragma unroll
            for (int i = 0; i < 8; i++)
#pragma unroll
                for (int j = 0; j < 4; j++) acc[i][j] = fmaf(a[i], w[j], acc[i][j]);
        }
    }
    float b4[4];
#pragma unroll
    for (int j = 0; j < 4; j++) b4[j] = bo[tx * 4 + j];
#pragma unroll
    for (int i = 0; i < 8; i++) {
        int r = row0 + ty * 8 + i;
        if (r < NN) {
            float4 v;
            v.x = acc[i][0] + b4[0];
            v.y = acc[i][1] + b4[1];
            v.z = acc[i][2] + b4[2];
            v.w = acc[i][3] + b4[3];
            *(float4*)(Out + (size_t)r * DOUT + tx * 4) = v;
        }
    }
}

// ---------------- launch ----------------
extern "C" void kernel_launch(void* const* d_in, const int* in_sizes, int n_in,
                              void* d_out, int out_size) {
    const float* x     = (const float*)d_in[0];
    const void*  ei    = d_in[1];           // int32 or int64, detected on device
    const float* Wl    = (const float*)d_in[2];
    const float* bl    = (const float*)d_in[3];
    const float* Wr    = (const float*)d_in[4];
    const float* gamma = (const float*)d_in[5];
    const float* beta  = (const float*)d_in[6];
    const float* Wo    = (const float*)d_in[7];
    const float* bo    = (const float*)d_in[8];
    float* out = (float*)d_out;

    (void)in_sizes; (void)n_in; (void)out_size;

    k_detect_init<<<NSB, 256>>>(ei);
    k_count<<<(EE + 255) / 256, 256>>>(ei);
    k_scan1<<<NSB, 256>>>();
    k_scan2<<<1, 512>>>();
    k_scan3<<<NSB, 256>>>();
    k_fill<<<(EE + 255) / 256, 256>>>(ei);

    int agg_blocks = (NN * 32 + 255) / 256;
    for (int l = 0; l < NL; l++) {
        int selIn  = (l == 0) ? 0 : ((l % 2 == 1) ? 1 : 2);
        int selOut = (l % 2 == 0) ? 1 : 2;
        k_agg<<<agg_blocks, 256>>>(x, selIn);
        k_gemm<<<GEMMB, 256>>>(x, selIn, selOut,
                               Wl + (size_t)l * D * D, bl + (size_t)l * D,
                               Wr + (size_t)l * D * D);
        if (l < NL - 1)
            k_norm<<<2000, 256>>>(selOut, gamma + (size_t)l * D, beta + (size_t)l * D);
    }
    // layer 4 BN+ReLU fused into the output projection (h lives in g_hA)
    k_out<<<GEMMB, 256>>>(gamma + (size_t)(NL - 1) * D, beta + (size_t)(NL - 1) * D,
                          Wo, bo, out);
}